// round 3
// baseline (speedup 1.0000x reference)
#include <cuda_runtime.h>
#include <cstdint>

#define IN_F  4096
#define OUT_F 16384
#define NB    8      // batch vectors
#define RPW   4      // rows per warp
#define WARPS 8
#define THREADS (WARPS * 32)          // 256
#define ROWS_PER_CTA (RPW * WARPS)    // 32
#define NCHUNK (IN_F / 128)           // 32 j-iterations (each lane: 4 cols per j)
#define NSTAGE 4
#define STAGE_B (RPW * 128 * 4)       // 2048 bytes per warp-stage
#define TAB_B   (16 * 32 * 4)         // 2048 bytes replicated NF4 table
#define SMEM_TOTAL (TAB_B + WARPS * NSTAGE * STAGE_B)   // 67584

__constant__ float NF4_CODE[16] = {
    -1.0f, -0.6961928009986877f, -0.5250730514526367f, -0.39491748809814453f,
    -0.28444138169288635f, -0.18477343022823334f, -0.09105003625154495f, 0.0f,
    0.07958029955625534f, 0.16093020141124725f, 0.24611230194568634f,
    0.33791524171829224f, 0.44070982933044434f, 0.5626170039176941f,
    0.7229568362236023f, 1.0f};

// ---- packed f32x2 helpers (Blackwell FFMA2 path: only reachable via PTX) ----
__device__ __forceinline__ unsigned long long pk2(float lo, float hi) {
    unsigned long long r;
    asm("mov.b64 %0, {%1, %2};" : "=l"(r)
        : "r"(__float_as_uint(lo)), "r"(__float_as_uint(hi)));
    return r;
}
__device__ __forceinline__ void upk2(unsigned long long v, float& lo, float& hi) {
    unsigned int a, b;
    asm("mov.b64 {%0, %1}, %2;" : "=r"(a), "=r"(b) : "l"(v));
    lo = __uint_as_float(a); hi = __uint_as_float(b);
}
__device__ __forceinline__ void fma2(unsigned long long& acc,
                                     unsigned long long a, unsigned long long b) {
    asm("fma.rn.f32x2 %0, %1, %2, %0;" : "+l"(acc) : "l"(a), "l"(b));
}
__device__ __forceinline__ unsigned long long mul2(unsigned long long a,
                                                   unsigned long long b) {
    unsigned long long r;
    asm("mul.rn.f32x2 %0, %1, %2;" : "=l"(r) : "l"(a), "l"(b));
    return r;
}

__global__ __launch_bounds__(THREADS, 2)
void nf4_qlinear_kernel(const float* __restrict__ x,
                        const int*   __restrict__ codes,
                        const float* __restrict__ absmax,
                        float*       __restrict__ out) {
    extern __shared__ char smem[];
    float* tab = reinterpret_cast<float*>(smem);   // tab[c*32+lane]: bank==lane
    const int tid  = threadIdx.x;
    const int lane = tid & 31;
    const int warp = tid >> 5;
    #pragma unroll
    for (int i = tid; i < 16 * 32; i += THREADS) tab[i] = NF4_CODE[i >> 5];
    __syncthreads();

    char* wbuf = smem + TAB_B + warp * (NSTAGE * STAGE_B);
    const unsigned wbuf_s =
        (unsigned)__cvta_generic_to_shared(wbuf);

    const int row0 = blockIdx.x * ROWS_PER_CTA + warp * RPW;

    // Stage loader: 4 rows x 16B/lane of codes for chunk jj -> slot
    auto issue_stage = [&](int jj, int slot) {
        #pragma unroll
        for (int r = 0; r < RPW; ++r) {
            const int* g = codes + (size_t)(row0 + r) * IN_F + jj * 128 + lane * 4;
            const unsigned d = wbuf_s + slot * STAGE_B + r * 512 + lane * 16;
            asm volatile("cp.async.cg.shared.global [%0], [%1], 16;\n"
                         :: "r"(d), "l"(g));
        }
        asm volatile("cp.async.commit_group;\n" ::: "memory");
    };

    // Prologue: fill NSTAGE-1 stages
    #pragma unroll
    for (int s = 0; s < NSTAGE - 1; ++s) issue_stage(s, s);

    unsigned long long acc[RPW][NB];
    #pragma unroll
    for (int r = 0; r < RPW; ++r)
        #pragma unroll
        for (int b = 0; b < NB; ++b) acc[r][b] = 0ULL;

    for (int j = 0; j < NCHUNK; ++j) {
        // stage j complete when <= NSTAGE-2 groups outstanding
        asm volatile("cp.async.wait_group %0;\n" :: "n"(NSTAGE - 2) : "memory");
        const int slot = j & (NSTAGE - 1);
        const int col  = j * 128 + lane * 4;

        // Dequantize: each lane reads only the 16B it loaded itself
        unsigned long long w01[RPW], w23[RPW];
        #pragma unroll
        for (int r = 0; r < RPW; ++r) {
            const int4 cv = *reinterpret_cast<const int4*>(
                wbuf + slot * STAGE_B + r * 512 + lane * 16);
            const float2 amp = *reinterpret_cast<const float2*>(
                absmax + (size_t)(row0 + r) * (IN_F / 64) + j * 2);
            const float a = (lane < 16) ? amp.x : amp.y;
            const unsigned long long a2 = pk2(a, a);
            const unsigned long long t01 =
                pk2(tab[(cv.x << 5) + lane], tab[(cv.y << 5) + lane]);
            const unsigned long long t23 =
                pk2(tab[(cv.z << 5) + lane], tab[(cv.w << 5) + lane]);
            w01[r] = mul2(t01, a2);
            w23[r] = mul2(t23, a2);
        }

        // Kick off the next stage before the FMA block
        const int jn = j + NSTAGE - 1;
        if (jn < NCHUNK) issue_stage(jn, jn & (NSTAGE - 1));
        else asm volatile("cp.async.commit_group;\n" ::: "memory");

        // x per batch just-in-time (L1-resident), FMA into all rows
        #pragma unroll
        for (int b = 0; b < NB; ++b) {
            const float4 xv =
                *reinterpret_cast<const float4*>(x + b * IN_F + col);
            const unsigned long long x01 = pk2(xv.x, xv.y);
            const unsigned long long x23 = pk2(xv.z, xv.w);
            #pragma unroll
            for (int r = 0; r < RPW; ++r) {
                fma2(acc[r][b], w01[r], x01);
                fma2(acc[r][b], w23[r], x23);
            }
        }
    }

    // Reduce pairs, then warp-reduce, store out[b, row]
    #pragma unroll
    for (int r = 0; r < RPW; ++r) {
        #pragma unroll
        for (int b = 0; b < NB; ++b) {
            float lo, hi;
            upk2(acc[r][b], lo, hi);
            float s = lo + hi;
            #pragma unroll
            for (int off = 16; off > 0; off >>= 1)
                s += __shfl_xor_sync(0xffffffffu, s, off);
            if (lane == 0) out[(size_t)b * OUT_F + row0 + r] = s;
        }
    }
}

extern "C" void kernel_launch(void* const* d_in, const int* in_sizes, int n_in,
                              void* d_out, int out_size) {
    const float* x      = (const float*)d_in[0];   // [8,1,4096] f32
    const int*   codes  = (const int*)d_in[1];     // [16384,4096] i32 (0..15)
    const float* absmax = (const float*)d_in[2];   // [16384,64] f32
    float*       out    = (float*)d_out;           // [8,1,16384] f32

    (void)in_sizes; (void)n_in; (void)out_size;
    cudaFuncSetAttribute(nf4_qlinear_kernel,
                         cudaFuncAttributeMaxDynamicSharedMemorySize,
                         SMEM_TOTAL);
    nf4_qlinear_kernel<<<OUT_F / ROWS_PER_CTA, THREADS, SMEM_TOTAL>>>(
        x, codes, absmax, out);
}

// round 4
// speedup vs baseline: 1.3223x; 1.3223x over previous
#include <cuda_runtime.h>
#include <cstdint>

#define IN_F  4096
#define OUT_F 16384
#define NB    8      // batch vectors
#define RPW   4      // rows per warp
#define WARPS 8
#define THREADS (WARPS * 32)          // 256
#define ROWS_PER_CTA (RPW * WARPS)    // 32
#define NCHUNK (IN_F / 128)           // 32 j-iterations (4 cols/lane each)

__constant__ float NF4_CODE[16] = {
    -1.0f, -0.6961928009986877f, -0.5250730514526367f, -0.39491748809814453f,
    -0.28444138169288635f, -0.18477343022823334f, -0.09105003625154495f, 0.0f,
    0.07958029955625534f, 0.16093020141124725f, 0.24611230194568634f,
    0.33791524171829224f, 0.44070982933044434f, 0.5626170039176941f,
    0.7229568362236023f, 1.0f};

// ---- packed f32x2 helpers (Blackwell FFMA2 path: only reachable via PTX) ----
__device__ __forceinline__ unsigned long long pk2(float lo, float hi) {
    unsigned long long r;
    asm("mov.b64 %0, {%1, %2};" : "=l"(r)
        : "r"(__float_as_uint(lo)), "r"(__float_as_uint(hi)));
    return r;
}
__device__ __forceinline__ void upk2(unsigned long long v, float& lo, float& hi) {
    unsigned int a, b;
    asm("mov.b64 {%0, %1}, %2;" : "=r"(a), "=r"(b) : "l"(v));
    lo = __uint_as_float(a); hi = __uint_as_float(b);
}
__device__ __forceinline__ void fma2(unsigned long long& acc,
                                     unsigned long long a, unsigned long long b) {
    asm("fma.rn.f32x2 %0, %1, %2, %0;" : "+l"(acc) : "l"(a), "l"(b));
}
__device__ __forceinline__ unsigned long long mul2(unsigned long long a,
                                                   unsigned long long b) {
    unsigned long long r;
    asm("mul.rn.f32x2 %0, %1, %2;" : "=l"(r) : "l"(a), "l"(b));
    return r;
}

__global__ __launch_bounds__(THREADS, 2)
void nf4_qlinear_kernel(const float* __restrict__ x,
                        const int*   __restrict__ codes,
                        const float* __restrict__ absmax,
                        float*       __restrict__ out) {
    // NF4 table replicated per lane: tab[c*32 + lane] -> bank == lane
    __shared__ float tab[16 * 32];
    const int tid  = threadIdx.x;
    const int lane = tid & 31;
    const int warp = tid >> 5;
    #pragma unroll
    for (int i = tid; i < 16 * 32; i += THREADS) tab[i] = NF4_CODE[i >> 5];
    __syncthreads();

    const int row0 = blockIdx.x * ROWS_PER_CTA + warp * RPW;
    const int sel_hi = (lane >= 16);   // which half of each 64-block pair

    unsigned long long acc[RPW][NB];
    #pragma unroll
    for (int r = 0; r < RPW; ++r)
        #pragma unroll
        for (int b = 0; b < NB; ++b) acc[r][b] = 0ULL;

    for (int j = 0; j < NCHUNK; j += 2) {
        const int colA = j * 128 + lane * 4;
        const int colB = colA + 128;

        // ---- Front-batched burst: 8 independent code LDG.128 + 4 absmax ----
        int4 cvA[RPW], cvB[RPW];
        float4 am[RPW];   // absmax blocks 2j..2j+3 for each row (covers A and B)
        #pragma unroll
        for (int r = 0; r < RPW; ++r) {
            const size_t base = (size_t)(row0 + r) * IN_F;
            cvA[r] = __ldcs(reinterpret_cast<const int4*>(codes + base + colA));
            cvB[r] = __ldcs(reinterpret_cast<const int4*>(codes + base + colB));
            am[r]  = *reinterpret_cast<const float4*>(
                         absmax + (size_t)(row0 + r) * (IN_F / 64) + j * 2);
        }

        // ---- Chunk A: dequant ----
        unsigned long long w01[RPW], w23[RPW];
        #pragma unroll
        for (int r = 0; r < RPW; ++r) {
            const float a = sel_hi ? am[r].y : am[r].x;
            const unsigned long long a2 = pk2(a, a);
            w01[r] = mul2(pk2(tab[(cvA[r].x << 5) + lane],
                              tab[(cvA[r].y << 5) + lane]), a2);
            w23[r] = mul2(pk2(tab[(cvA[r].z << 5) + lane],
                              tab[(cvA[r].w << 5) + lane]), a2);
        }
        // ---- Chunk A: FMA over batches ----
        #pragma unroll
        for (int b = 0; b < NB; ++b) {
            const float4 xv =
                *reinterpret_cast<const float4*>(x + b * IN_F + colA);
            const unsigned long long x01 = pk2(xv.x, xv.y);
            const unsigned long long x23 = pk2(xv.z, xv.w);
            #pragma unroll
            for (int r = 0; r < RPW; ++r) {
                fma2(acc[r][b], w01[r], x01);
                fma2(acc[r][b], w23[r], x23);
            }
        }

        // ---- Chunk B: dequant ----
        #pragma unroll
        for (int r = 0; r < RPW; ++r) {
            const float a = sel_hi ? am[r].w : am[r].z;
            const unsigned long long a2 = pk2(a, a);
            w01[r] = mul2(pk2(tab[(cvB[r].x << 5) + lane],
                              tab[(cvB[r].y << 5) + lane]), a2);
            w23[r] = mul2(pk2(tab[(cvB[r].z << 5) + lane],
                              tab[(cvB[r].w << 5) + lane]), a2);
        }
        // ---- Chunk B: FMA over batches ----
        #pragma unroll
        for (int b = 0; b < NB; ++b) {
            const float4 xv =
                *reinterpret_cast<const float4*>(x + b * IN_F + colB);
            const unsigned long long x01 = pk2(xv.x, xv.y);
            const unsigned long long x23 = pk2(xv.z, xv.w);
            #pragma unroll
            for (int r = 0; r < RPW; ++r) {
                fma2(acc[r][b], w01[r], x01);
                fma2(acc[r][b], w23[r], x23);
            }
        }
    }

    // Reduce pairs, then warp-reduce, store out[b, row]
    #pragma unroll
    for (int r = 0; r < RPW; ++r) {
        #pragma unroll
        for (int b = 0; b < NB; ++b) {
            float lo, hi;
            upk2(acc[r][b], lo, hi);
            float s = lo + hi;
            #pragma unroll
            for (int off = 16; off > 0; off >>= 1)
                s += __shfl_xor_sync(0xffffffffu, s, off);
            if (lane == 0) out[(size_t)b * OUT_F + row0 + r] = s;
        }
    }
}

extern "C" void kernel_launch(void* const* d_in, const int* in_sizes, int n_in,
                              void* d_out, int out_size) {
    const float* x      = (const float*)d_in[0];   // [8,1,4096] f32
    const int*   codes  = (const int*)d_in[1];     // [16384,4096] i32 (0..15)
    const float* absmax = (const float*)d_in[2];   // [16384,64] f32
    float*       out    = (float*)d_out;           // [8,1,16384] f32

    (void)in_sizes; (void)n_in; (void)out_size;
    nf4_qlinear_kernel<<<OUT_F / ROWS_PER_CTA, THREADS>>>(x, codes, absmax, out);
}

// round 5
// speedup vs baseline: 1.5959x; 1.2069x over previous
#include <cuda_runtime.h>
#include <cstdint>

#define IN_F  4096
#define OUT_F 16384
#define NB    8      // batch vectors
#define NP    (NB/2) // batch pairs
#define RPW   4      // rows per warp
#define WARPS 8
#define THREADS (WARPS * 32)          // 256
#define ROWS_PER_CTA (RPW * WARPS)    // 32
#define NCHUNK (IN_F / 128)           // 32 j-iterations (4 cols/lane each)

__constant__ float NF4_CODE[16] = {
    -1.0f, -0.6961928009986877f, -0.5250730514526367f, -0.39491748809814453f,
    -0.28444138169288635f, -0.18477343022823334f, -0.09105003625154495f, 0.0f,
    0.07958029955625534f, 0.16093020141124725f, 0.24611230194568634f,
    0.33791524171829224f, 0.44070982933044434f, 0.5626170039176941f,
    0.7229568362236023f, 1.0f};

// ---- packed f32x2 helpers (Blackwell FFMA2 path: only reachable via PTX) ----
__device__ __forceinline__ unsigned long long pk2(float lo, float hi) {
    unsigned long long r;
    asm("mov.b64 %0, {%1, %2};" : "=l"(r)
        : "r"(__float_as_uint(lo)), "r"(__float_as_uint(hi)));
    return r;
}
__device__ __forceinline__ void upk2(unsigned long long v, float& lo, float& hi) {
    unsigned int a, b;
    asm("mov.b64 {%0, %1}, %2;" : "=r"(a), "=r"(b) : "l"(v));
    lo = __uint_as_float(a); hi = __uint_as_float(b);
}
__device__ __forceinline__ void fma2(unsigned long long& acc,
                                     unsigned long long a, unsigned long long b) {
    asm("fma.rn.f32x2 %0, %1, %2, %0;" : "+l"(acc) : "l"(a), "l"(b));
}

__global__ __launch_bounds__(THREADS, 2)
void nf4_qlinear_kernel(const float* __restrict__ x,
                        const int*   __restrict__ codes,
                        const float* __restrict__ absmax,
                        float*       __restrict__ out) {
    // NF4 table replicated per lane: tab[c*32 + lane] -> bank == lane
    __shared__ float tab[16 * 32];
    const int tid  = threadIdx.x;
    const int lane = tid & 31;
    const int warp = tid >> 5;
    #pragma unroll
    for (int i = tid; i < 16 * 32; i += THREADS) tab[i] = NF4_CODE[i >> 5];
    __syncthreads();

    const int row0 = blockIdx.x * ROWS_PER_CTA + warp * RPW;
    const int sel_hi = (lane >= 16);   // which half of each 64-block pair

    // acc[r][p] packs (batch 2p, batch 2p+1) partial dot products
    unsigned long long acc[RPW][NP];
    #pragma unroll
    for (int r = 0; r < RPW; ++r)
        #pragma unroll
        for (int p = 0; p < NP; ++p) acc[r][p] = 0ULL;

    for (int j = 0; j < NCHUNK; j += 2) {
        const int colA = j * 128 + lane * 4;
        const int colB = colA + 128;

        // ---- Front-batched burst: 8 independent code LDG.128 + 4 absmax ----
        int4 cvA[RPW], cvB[RPW];
        float4 am[RPW];   // absmax blocks 2j..2j+3 per row (covers A and B)
        #pragma unroll
        for (int r = 0; r < RPW; ++r) {
            const size_t base = (size_t)(row0 + r) * IN_F;
            cvA[r] = __ldcs(reinterpret_cast<const int4*>(codes + base + colA));
            cvB[r] = __ldcs(reinterpret_cast<const int4*>(codes + base + colB));
            am[r]  = *reinterpret_cast<const float4*>(
                         absmax + (size_t)(row0 + r) * (IN_F / 64) + j * 2);
        }

        // ================= Chunk A =================
        {
            // cross-batch x pairs for this chunk's 4 columns (reused by all rows)
            unsigned long long xp[NP][4];
            #pragma unroll
            for (int p = 0; p < NP; ++p) {
                const float4 xe = *reinterpret_cast<const float4*>(
                    x + (2 * p)     * IN_F + colA);
                const float4 xo = *reinterpret_cast<const float4*>(
                    x + (2 * p + 1) * IN_F + colA);
                xp[p][0] = pk2(xe.x, xo.x);
                xp[p][1] = pk2(xe.y, xo.y);
                xp[p][2] = pk2(xe.z, xo.z);
                xp[p][3] = pk2(xe.w, xo.w);
            }
            #pragma unroll
            for (int r = 0; r < RPW; ++r) {
                const float a = sel_hi ? am[r].y : am[r].x;
                const float w0 = tab[(cvA[r].x << 5) + lane] * a;
                const float w1 = tab[(cvA[r].y << 5) + lane] * a;
                const float w2 = tab[(cvA[r].z << 5) + lane] * a;
                const float w3 = tab[(cvA[r].w << 5) + lane] * a;
                const unsigned long long ws[4] = {
                    pk2(w0, w0), pk2(w1, w1), pk2(w2, w2), pk2(w3, w3)};
                #pragma unroll
                for (int p = 0; p < NP; ++p) {
                    fma2(acc[r][p], ws[0], xp[p][0]);
                    fma2(acc[r][p], ws[1], xp[p][1]);
                    fma2(acc[r][p], ws[2], xp[p][2]);
                    fma2(acc[r][p], ws[3], xp[p][3]);
                }
            }
        }

        // ================= Chunk B =================
        {
            unsigned long long xp[NP][4];
            #pragma unroll
            for (int p = 0; p < NP; ++p) {
                const float4 xe = *reinterpret_cast<const float4*>(
                    x + (2 * p)     * IN_F + colB);
                const float4 xo = *reinterpret_cast<const float4*>(
                    x + (2 * p + 1) * IN_F + colB);
                xp[p][0] = pk2(xe.x, xo.x);
                xp[p][1] = pk2(xe.y, xo.y);
                xp[p][2] = pk2(xe.z, xo.z);
                xp[p][3] = pk2(xe.w, xo.w);
            }
            #pragma unroll
            for (int r = 0; r < RPW; ++r) {
                const float a = sel_hi ? am[r].w : am[r].z;
                const float w0 = tab[(cvB[r].x << 5) + lane] * a;
                const float w1 = tab[(cvB[r].y << 5) + lane] * a;
                const float w2 = tab[(cvB[r].z << 5) + lane] * a;
                const float w3 = tab[(cvB[r].w << 5) + lane] * a;
                const unsigned long long ws[4] = {
                    pk2(w0, w0), pk2(w1, w1), pk2(w2, w2), pk2(w3, w3)};
                #pragma unroll
                for (int p = 0; p < NP; ++p) {
                    fma2(acc[r][p], ws[0], xp[p][0]);
                    fma2(acc[r][p], ws[1], xp[p][1]);
                    fma2(acc[r][p], ws[2], xp[p][2]);
                    fma2(acc[r][p], ws[3], xp[p][3]);
                }
            }
        }
    }

    // Warp-reduce each packed accumulator (both batches at once), store.
    #pragma unroll
    for (int r = 0; r < RPW; ++r) {
        #pragma unroll
        for (int p = 0; p < NP; ++p) {
            float se, so;
            upk2(acc[r][p], se, so);
            #pragma unroll
            for (int off = 16; off > 0; off >>= 1) {
                se += __shfl_xor_sync(0xffffffffu, se, off);
                so += __shfl_xor_sync(0xffffffffu, so, off);
            }
            if (lane == 0) {
                out[(size_t)(2 * p)     * OUT_F + row0 + r] = se;
                out[(size_t)(2 * p + 1) * OUT_F + row0 + r] = so;
            }
        }
    }
}

extern "C" void kernel_launch(void* const* d_in, const int* in_sizes, int n_in,
                              void* d_out, int out_size) {
    const float* x      = (const float*)d_in[0];   // [8,1,4096] f32
    const int*   codes  = (const int*)d_in[1];     // [16384,4096] i32 (0..15)
    const float* absmax = (const float*)d_in[2];   // [16384,64] f32
    float*       out    = (float*)d_out;           // [8,1,16384] f32

    (void)in_sizes; (void)n_in; (void)out_size;
    nf4_qlinear_kernel<<<OUT_F / ROWS_PER_CTA, THREADS>>>(x, codes, absmax, out);
}